// round 15
// baseline (speedup 1.0000x reference)
#include <cuda_runtime.h>
#include <cuda_fp16.h>
#include <math.h>
#include <stdint.h>

#define BB 2
#define SS 2048
#define DD 1024
#define HH 16
#define HD 64
#define MROWS (BB*SS)     // 4096
#define NPROJ (HH*3*HD)   // 3072

// ---------------- scratch ----------------------------------------------------
__device__ __align__(16) __half g_a16[(size_t)MROWS * DD];
__device__ __align__(16) __half g_wT_in[(size_t)NPROJ * DD];
__device__ __align__(16) __half g_wT_out[(size_t)DD * DD];
__device__ __align__(16) __half g_proj[(size_t)MROWS * NPROJ];
__device__ __align__(16) __half g_q16[(size_t)BB * HH * SS * HD];
__device__ __align__(16) __half g_k16[(size_t)BB * HH * SS * HD];
__device__ __align__(16) __half g_v16[(size_t)BB * HH * SS * HD];
__device__ __align__(16) __half g_x16[(size_t)MROWS * DD];
__device__ __align__(16) float2 g_sc[(size_t)MROWS * 32];   // (sin,cos) per (row, i)

// ---------------- PTX helpers ------------------------------------------------
__device__ __forceinline__ uint32_t smem_addr(const void* p) {
    return (uint32_t)__cvta_generic_to_shared(p);
}
__device__ __forceinline__ void cp16(uint32_t s, const void* g) {
    asm volatile("cp.async.cg.shared.global [%0], [%1], 16;\n" :: "r"(s), "l"(g));
}
__device__ __forceinline__ void cp_commit() { asm volatile("cp.async.commit_group;\n"); }
__device__ __forceinline__ void cp_wait1()  { asm volatile("cp.async.wait_group 1;\n"); }

__device__ __forceinline__ void ldm4(uint32_t& r0, uint32_t& r1, uint32_t& r2, uint32_t& r3, uint32_t a) {
    asm volatile("ldmatrix.sync.aligned.m8n8.x4.shared.b16 {%0,%1,%2,%3},[%4];\n"
                 : "=r"(r0), "=r"(r1), "=r"(r2), "=r"(r3) : "r"(a));
}
__device__ __forceinline__ void ldm4t(uint32_t& r0, uint32_t& r1, uint32_t& r2, uint32_t& r3, uint32_t a) {
    asm volatile("ldmatrix.sync.aligned.m8n8.x4.trans.shared.b16 {%0,%1,%2,%3},[%4];\n"
                 : "=r"(r0), "=r"(r1), "=r"(r2), "=r"(r3) : "r"(a));
}
__device__ __forceinline__ void mma16816(float* c,
    uint32_t a0, uint32_t a1, uint32_t a2, uint32_t a3, uint32_t b0, uint32_t b1) {
    asm volatile("mma.sync.aligned.m16n8k16.row.col.f32.f16.f16.f32 "
                 "{%0,%1,%2,%3},{%4,%5,%6,%7},{%8,%9},{%0,%1,%2,%3};\n"
                 : "+f"(c[0]), "+f"(c[1]), "+f"(c[2]), "+f"(c[3])
                 : "r"(a0), "r"(a1), "r"(a2), "r"(a3), "r"(b0), "r"(b1));
}
__device__ __forceinline__ float ex2f(float x) {
    float y; asm("ex2.approx.f32 %0,%1;\n" : "=f"(y) : "f"(x)); return y;
}
__device__ __forceinline__ uint32_t cvt_h2(float a, float b) {
    uint32_t r;
    asm("cvt.rn.f16x2.f32 %0, %1, %2;\n" : "=r"(r) : "f"(b), "f"(a));
    return r;
}
__device__ __forceinline__ uint32_t ex2_h2(uint32_t x) {
    uint32_t r;
    asm("ex2.approx.f16x2 %0, %1;\n" : "=r"(r) : "r"(x));
    return r;
}

#define L2E 1.4426950408889634f

// ---------------- convert f32 -> f16 ----------------------------------------
__global__ void cvt16_kernel(const float* __restrict__ A, __half* __restrict__ O) {
    int i = blockIdx.x * blockDim.x + threadIdx.x;
    float2 v = ((const float2*)A)[i];
    ((__half2*)O)[i] = __float22half2_rn(v);
}

// ---------------- transpose + convert: WT[c][r] = W[r][c] -------------------
__global__ void transcvt_kernel(const float* __restrict__ W, __half* __restrict__ WT,
                                int R, int C) {
    __shared__ float t[32][33];
    int c0 = blockIdx.x * 32, r0 = blockIdx.y * 32;
    int x = threadIdx.x, y = threadIdx.y;
#pragma unroll
    for (int i = 0; i < 32; i += 8)
        t[y + i][x] = W[(size_t)(r0 + y + i) * C + c0 + x];
    __syncthreads();
#pragma unroll
    for (int i = 0; i < 32; i += 8)
        WT[(size_t)(c0 + y + i) * R + r0 + x] = __float2half(t[x][y + i]);
}

// ---------------- sin/cos table: one entry per (row, i) ---------------------
__global__ void sincos_table(const int* __restrict__ segpos, float2* __restrict__ sc) {
    int idx = blockIdx.x * blockDim.x + threadIdx.x;   // over MROWS*32
    int i = idx & 31, row = idx >> 5;
    int pos = segpos[row];
    // 10000^(-i/32) = exp2(-i * log2(10000)/32)
    float inv = ex2f(-(float)i * 0.41524101186092037f);
    float ang = (float)pos * inv;
    float sn, cs;
    sincosf(ang, &sn, &cs);
    sc[idx] = make_float2(sn, cs);
}

// ---------------- HGEMM: C = A * B^T, BK=32, 3-stage, single-sync -----------
#define GST 40
#define HSTG (128 * GST)
template <typename OT>
__global__ __launch_bounds__(256, 2) void hgemm(
    const __half* __restrict__ A, const __half* __restrict__ B,
    OT* __restrict__ C, int M, int N, int K)
{
    extern __shared__ __half hsm[];
    __half* As = hsm;                 // 3 stages
    __half* Bs = hsm + 3 * HSTG;

    const int tid = threadIdx.x, lane = tid & 31, w = tid >> 5;
    const int wm = w & 1, wn = w >> 1;
    const int bx = blockIdx.x, by = blockIdx.y;
    const int nk = K >> 5;
    const int lrow = tid >> 2, lcol = (tid & 3) * 8;

    const __half* Ag = A + (size_t)(by * 128 + lrow) * K + lcol;
    const __half* Bg = B + (size_t)(bx * 128 + lrow) * K + lcol;
    const uint32_t sa0 = smem_addr(&As[lrow * GST + lcol]);
    const uint32_t sb0 = smem_addr(&Bs[lrow * GST + lcol]);
    const uint32_t stagesz = (uint32_t)(HSTG * sizeof(__half));

    float acc[4][4][4];
#pragma unroll
    for (int a = 0; a < 4; a++)
#pragma unroll
        for (int b = 0; b < 4; b++)
#pragma unroll
            for (int c = 0; c < 4; c++) acc[a][b][c] = 0.0f;

    // prologue: k-blocks 0,1 -> stages 0,1 (groups g0,g1)
#pragma unroll
    for (int p = 0; p < 2; p++) {
        const __half* ag = Ag + p * 32;
        const __half* bg = Bg + p * 32;
        cp16(sa0 + p * stagesz, ag);
        cp16(sa0 + p * stagesz + 64 * GST * 2, ag + (size_t)64 * K);
        cp16(sb0 + p * stagesz, bg);
        cp16(sb0 + p * stagesz + 64 * GST * 2, bg + (size_t)64 * K);
        cp_commit();
    }

    int st_r = 0;                      // kb % 3
    for (int kb = 0; kb < nk; kb++) {
        cp_wait1();                    // own copies for g_kb complete
        __syncthreads();               // ALL threads' g_kb complete; compute(kb-1) done
        int st_w = st_r - 1; if (st_w < 0) st_w = 2;
        if (kb + 2 < nk) {
            const __half* ag = Ag + (kb + 2) * 32;
            const __half* bg = Bg + (kb + 2) * 32;
            cp16(sa0 + st_w * stagesz, ag);
            cp16(sa0 + st_w * stagesz + 64 * GST * 2, ag + (size_t)64 * K);
            cp16(sb0 + st_w * stagesz, bg);
            cp16(sb0 + st_w * stagesz + 64 * GST * 2, bg + (size_t)64 * K);
        }
        cp_commit();                   // g_{kb+2}

        const __half* as = As + st_r * HSTG;
        const __half* bs = Bs + st_r * HSTG;
#pragma unroll
        for (int ks = 0; ks < 2; ks++) {
            uint32_t aq[4][4];
#pragma unroll
            for (int mi = 0; mi < 4; mi++) {
                uint32_t ad = smem_addr(as + (wm * 64 + mi * 16 + (lane & 15)) * GST
                                        + ks * 16 + 8 * (lane >> 4));
                ldm4(aq[mi][0], aq[mi][1], aq[mi][2], aq[mi][3], ad);
            }
#pragma unroll
            for (int nj = 0; nj < 2; nj++) {
                uint32_t b0, b1, b2, b3;
                uint32_t bd = smem_addr(bs + (wn * 32 + nj * 16 + (lane & 7) + 8 * (lane >> 4)) * GST
                                        + ks * 16 + 8 * ((lane >> 3) & 1));
                ldm4(b0, b1, b2, b3, bd);
#pragma unroll
                for (int mi = 0; mi < 4; mi++) {
                    mma16816(acc[mi][2 * nj],     aq[mi][0], aq[mi][1], aq[mi][2], aq[mi][3], b0, b1);
                    mma16816(acc[mi][2 * nj + 1], aq[mi][0], aq[mi][1], aq[mi][2], aq[mi][3], b2, b3);
                }
            }
        }
        st_r = (st_r == 2) ? 0 : st_r + 1;
    }

    // epilogue
#pragma unroll
    for (int mi = 0; mi < 4; mi++) {
#pragma unroll
        for (int ni = 0; ni < 4; ni++) {
            int row = by * 128 + wm * 64 + mi * 16 + (lane >> 2);
            int col = bx * 128 + wn * 32 + ni * 8 + 2 * (lane & 3);
            if (sizeof(OT) == 4) {
                *(float2*)((float*)C + (size_t)row * N + col) =
                    make_float2(acc[mi][ni][0], acc[mi][ni][1]);
                *(float2*)((float*)C + (size_t)(row + 8) * N + col) =
                    make_float2(acc[mi][ni][2], acc[mi][ni][3]);
            } else {
                *(__half2*)((__half*)C + (size_t)row * N + col) =
                    __float22half2_rn(make_float2(acc[mi][ni][0], acc[mi][ni][1]));
                *(__half2*)((__half*)C + (size_t)(row + 8) * N + col) =
                    __float22half2_rn(make_float2(acc[mi][ni][2], acc[mi][ni][3]));
            }
        }
    }
}

// ---------------- RoPE apply (table lookup) ---------------------------------
__global__ __launch_bounds__(256) void rope_kernel(
    const __half* __restrict__ proj, const float2* __restrict__ sc,
    __half* __restrict__ q, __half* __restrict__ k, __half* __restrict__ v)
{
    int idx = blockIdx.x * blockDim.x + threadIdx.x;
    int i = idx & 31;
    int h = (idx >> 5) & 15;
    int s = (idx >> 9) & 2047;
    int b = idx >> 20;

    int row = b * SS + s;
    const __half* p = proj + (size_t)row * NPROJ + h * (3 * HD);

    float2 t = sc[row * 32 + i];
    float sn = t.x, cs = t.y;

    float qf = __half2float(p[i]),          qs = __half2float(p[i + 32]);
    float kf = __half2float(p[HD + i]),     ks = __half2float(p[HD + i + 32]);
    __half vf = p[2 * HD + i],              vs = p[2 * HD + i + 32];

    const float qscale = 0.125f;
    size_t ob = ((size_t)(b * HH + h) * SS + s) * HD;
    q[ob + i]      = __float2half((qf * cs - qs * sn) * qscale);
    q[ob + i + 32] = __float2half((qs * cs + qf * sn) * qscale);
    k[ob + i]      = __float2half(kf * cs - ks * sn);
    k[ob + i + 32] = __float2half(ks * cs + kf * sn);
    v[ob + i]      = vf;
    v[ob + i + 32] = vs;
}

// ---------------- Flash attention: 128-row chunks, h2-exp + mma row-sum -----
#define FST 72
#define QSZ (128 * FST)
#define KVCH (128 * FST)
__global__ __launch_bounds__(256, 2) void flash16(
    const __half* __restrict__ Q, const __half* __restrict__ K,
    const __half* __restrict__ V, __half* __restrict__ X)
{
    extern __shared__ __half fsm[];
    __half* sQ = fsm;
    __half* sKs[2] = { fsm + QSZ, fsm + QSZ + KVCH };
    __half* sVs[2] = { fsm + QSZ + 2 * KVCH, fsm + QSZ + 3 * KVCH };

    const int tid = threadIdx.x, lane = tid & 31, w = tid >> 5;
    const int qb = (int)gridDim.x - 1 - (int)blockIdx.x;   // long CTAs first
    const int h = blockIdx.y, b = blockIdx.z;
    const int q0 = qb * 128, m0 = w * 16;
    const size_t base = (size_t)(b * HH + h) * SS * HD;

    const int lr = tid >> 3, lc = (tid & 7) * 8;

    // prologue: Q + KV chunk 0 -> one group
    {
#pragma unroll
        for (int p = 0; p < 4; p++) {
            cp16(smem_addr(&sQ[(lr + p * 32) * FST + lc]),
                 Q + base + (size_t)(q0 + lr + p * 32) * HD + lc);
            cp16(smem_addr(&sKs[0][(lr + p * 32) * FST + lc]),
                 K + base + (size_t)(lr + p * 32) * HD + lc);
            cp16(smem_addr(&sVs[0][(lr + p * 32) * FST + lc]),
                 V + base + (size_t)(lr + p * 32) * HD + lc);
        }
        cp_commit();
    }

    uint32_t aq[4][4];
    float Ov[8][4];
#pragma unroll
    for (int t = 0; t < 8; t++)
#pragma unroll
        for (int c = 0; c < 4; c++) Ov[t][c] = 0.0f;
    float mA = -1e30f, mB = -1e30f, lA = 0.0f, lB = 0.0f;

    const int nch = qb + 1;
    for (int ch = 0; ch < nch; ch++) {
        if (ch + 1 < nch) {
            int st = (ch + 1) & 1;
#pragma unroll
            for (int p = 0; p < 4; p++) {
                cp16(smem_addr(&sKs[st][(lr + p * 32) * FST + lc]),
                     K + base + (size_t)((ch + 1) * 128 + lr + p * 32) * HD + lc);
                cp16(smem_addr(&sVs[st][(lr + p * 32) * FST + lc]),
                     V + base + (size_t)((ch + 1) * 128 + lr + p * 32) * HD + lc);
            }
        }
        cp_commit();
        cp_wait1();
        __syncthreads();

        if (ch == 0) {
#pragma unroll
            for (int ks = 0; ks < 4; ks++) {
                uint32_t ad = smem_addr(&sQ[(m0 + (lane & 15)) * FST + ks * 16 + 8 * (lane >> 4)]);
                ldm4(aq[ks][0], aq[ks][1], aq[ks][2], aq[ks][3], ad);
            }
        }

        const __half* sKc = sKs[ch & 1];
        const __half* sVc = sVs[ch & 1];

#pragma unroll
        for (int sub = 0; sub < 2; sub++) {
            const int kv0 = ch * 128 + sub * 64;
            if (kv0 > q0 + m0 + 15) continue;      // warp rows fully masked
            const __half* sK = sKc + sub * 64 * FST;
            const __half* sV = sVc + sub * 64 * FST;

            float Sv[8][4];
#pragma unroll
            for (int t = 0; t < 8; t++)
#pragma unroll
                for (int c = 0; c < 4; c++) Sv[t][c] = 0.0f;

#pragma unroll
            for (int ks = 0; ks < 4; ks++) {
#pragma unroll
                for (int ng = 0; ng < 4; ng++) {
                    uint32_t b0, b1, b2, b3;
                    uint32_t bd = smem_addr(&sK[(ng * 16 + (lane & 7) + 8 * (lane >> 4)) * FST
                                                + ks * 16 + 8 * ((lane >> 3) & 1)]);
                    ldm4(b0, b1, b2, b3, bd);
                    mma16816(Sv[2 * ng],     aq[ks][0], aq[ks][1], aq[ks][2], aq[ks][3], b0, b1);
                    mma16816(Sv[2 * ng + 1], aq[ks][0], aq[ks][1], aq[ks][2], aq[ks][3], b2, b3);
                }
            }

            // softcap (poly tanh) + causal mask
            const bool domask = (kv0 + 63 > q0 + m0);
            const int rAg = q0 + m0 + (lane >> 2);
            const int rBg = rAg + 8;
#pragma unroll
            for (int t = 0; t < 8; t++) {
                int cg = kv0 + t * 8 + 2 * (lane & 3);
#pragma unroll
                for (int c = 0; c < 4; c++) {
                    float s = Sv[t][c];
                    float x = 0.02f * s;
                    float x2 = x * x;
                    s = fmaf(s * x2, fmaf(0.13333334f, x2, -0.33333334f), s);
                    if (domask) {
                        int colg = cg + (c & 1);
                        int rowg = (c < 2) ? rAg : rBg;
                        if (colg > rowg) s = -1e30f;
                    }
                    Sv[t][c] = s;
                }
            }

            // online softmax: row max
            float tmA = -1e30f, tmB = -1e30f;
#pragma unroll
            for (int t = 0; t < 8; t++) {
                tmA = fmaxf(tmA, fmaxf(Sv[t][0], Sv[t][1]));
                tmB = fmaxf(tmB, fmaxf(Sv[t][2], Sv[t][3]));
            }
            tmA = fmaxf(tmA, __shfl_xor_sync(0xffffffffu, tmA, 1));
            tmA = fmaxf(tmA, __shfl_xor_sync(0xffffffffu, tmA, 2));
            tmB = fmaxf(tmB, __shfl_xor_sync(0xffffffffu, tmB, 1));
            tmB = fmaxf(tmB, __shfl_xor_sync(0xffffffffu, tmB, 2));
            float mnA = fmaxf(mA, tmA), mnB = fmaxf(mB, tmB);
            float alA = ex2f((mA - mnA) * L2E);
            float alB = ex2f((mB - mnB) * L2E);
            mA = mnA; mB = mnB;
            float mlA = mnA * L2E, mlB = mnB * L2E;

            // exp via f16x2 MUFU; results ARE the PV A-fragments
            uint32_t Pa[8], Pb[8];
#pragma unroll
            for (int t = 0; t < 8; t++) {
                float eA0 = fmaf(Sv[t][0], L2E, -mlA);
                float eA1 = fmaf(Sv[t][1], L2E, -mlA);
                float eB0 = fmaf(Sv[t][2], L2E, -mlB);
                float eB1 = fmaf(Sv[t][3], L2E, -mlB);
                Pa[t] = ex2_h2(cvt_h2(eA0, eA1));
                Pb[t] = ex2_h2(cvt_h2(eB0, eB1));
            }

            // row sums via mma with all-ones B
            float sacc[4] = {0.0f, 0.0f, 0.0f, 0.0f};
            const uint32_t ones2 = 0x3C003C00u;
#pragma unroll
            for (int ks2 = 0; ks2 < 4; ks2++)
                mma16816(sacc, Pa[2 * ks2], Pb[2 * ks2], Pa[2 * ks2 + 1], Pb[2 * ks2 + 1],
                         ones2, ones2);
            lA = lA * alA + sacc[0];
            lB = lB * alB + sacc[2];

#pragma unroll
            for (int t = 0; t < 8; t++) {
                Ov[t][0] *= alA; Ov[t][1] *= alA;
                Ov[t][2] *= alB; Ov[t][3] *= alB;
            }

            // PV
#pragma unroll
            for (int ks2 = 0; ks2 < 4; ks2++) {
                uint32_t a0 = Pa[2 * ks2];
                uint32_t a1 = Pb[2 * ks2];
                uint32_t a2 = Pa[2 * ks2 + 1];
                uint32_t a3 = Pb[2 * ks2 + 1];
#pragma unroll
                for (int dg = 0; dg < 4; dg++) {
                    uint32_t b0, b1, b2, b3;
                    uint32_t bd = smem_addr(&sV[(ks2 * 16 + (lane & 7) + 8 * ((lane >> 3) & 1)) * FST
                                                + dg * 16 + 8 * (lane >> 4)]);
                    ldm4t(b0, b1, b2, b3, bd);
                    mma16816(Ov[2 * dg],     a0, a1, a2, a3, b0, b1);
                    mma16816(Ov[2 * dg + 1], a0, a1, a2, a3, b2, b3);
                }
            }
        }
        __syncthreads();
    }

    // normalize + write x16[token][h*64 + d]
    float iA = 1.0f / lA, iB = 1.0f / lB;
    int rowA = b * SS + q0 + m0 + (lane >> 2);
#pragma unroll
    for (int t = 0; t < 8; t++) {
        int col = h * 64 + t * 8 + 2 * (lane & 3);
        *(__half2*)(X + (size_t)rowA * DD + col) =
            __float22half2_rn(make_float2(Ov[t][0] * iA, Ov[t][1] * iA));
        *(__half2*)(X + (size_t)(rowA + 8) * DD + col) =
            __float22half2_rn(make_float2(Ov[t][2] * iB, Ov[t][3] * iB));
    }
}

// ---------------- launch ----------------------------------------------------
extern "C" void kernel_launch(void* const* d_in, const int* in_sizes, int n_in,
                              void* d_out, int out_size)
{
    const float* inputs = (const float*)d_in[0];
    const int*   segpos = (const int*)d_in[1];
    const float* w_in   = (const float*)d_in[3];
    const float* w_out  = (const float*)d_in[4];
    float* out = (float*)d_out;

    __half *a16, *wTin, *wTout, *proj, *q16, *k16, *v16, *x16;
    float2* sc;
    cudaGetSymbolAddress((void**)&a16,  g_a16);
    cudaGetSymbolAddress((void**)&wTin, g_wT_in);
    cudaGetSymbolAddress((void**)&wTout,g_wT_out);
    cudaGetSymbolAddress((void**)&proj, g_proj);
    cudaGetSymbolAddress((void**)&q16,  g_q16);
    cudaGetSymbolAddress((void**)&k16,  g_k16);
    cudaGetSymbolAddress((void**)&v16,  g_v16);
    cudaGetSymbolAddress((void**)&x16,  g_x16);
    cudaGetSymbolAddress((void**)&sc,   g_sc);

    const int hgemm_smem = 3 * 2 * HSTG * (int)sizeof(__half);     // 61440
    const int flash_smem = (QSZ + 4 * KVCH) * (int)sizeof(__half); // 92160
    cudaFuncSetAttribute(hgemm<__half>, cudaFuncAttributeMaxDynamicSharedMemorySize, hgemm_smem);
    cudaFuncSetAttribute(hgemm<float>,  cudaFuncAttributeMaxDynamicSharedMemorySize, hgemm_smem);
    cudaFuncSetAttribute(flash16, cudaFuncAttributeMaxDynamicSharedMemorySize, flash_smem);

    // converts + trig table (independent of GEMM)
    cvt16_kernel<<<(MROWS * DD / 2) / 256, 256>>>(inputs, a16);
    transcvt_kernel<<<dim3(NPROJ / 32, DD / 32), dim3(32, 8)>>>(w_in, wTin, DD, NPROJ);
    transcvt_kernel<<<dim3(DD / 32, DD / 32), dim3(32, 8)>>>(w_out, wTout, DD, DD);
    sincos_table<<<(MROWS * 32) / 256, 256>>>(segpos, sc);

    // 1) QKV projection -> f16 proj
    hgemm<__half><<<dim3(NPROJ / 128, MROWS / 128), 256, hgemm_smem>>>(a16, wTin, proj, MROWS, NPROJ, DD);

    // 2) RoPE + split (table lookup)
    rope_kernel<<<(BB * SS * HH * 32) / 256, 256>>>(proj, sc, q16, k16, v16);

    // 3) flash attention
    flash16<<<dim3(SS / 128, HH, BB), 256, flash_smem>>>(q16, k16, v16, x16);

    // 4) output projection -> f32 out
    hgemm<float><<<dim3(DD / 128, MROWS / 128), 256, hgemm_smem>>>(x16, wTout, out, MROWS, DD, DD);
}

// round 16
// speedup vs baseline: 1.0063x; 1.0063x over previous
#include <cuda_runtime.h>
#include <cuda_fp16.h>
#include <math.h>
#include <stdint.h>

#define BB 2
#define SS 2048
#define DD 1024
#define HH 16
#define HD 64
#define MROWS (BB*SS)     // 4096
#define NPROJ (HH*3*HD)   // 3072

// ---------------- scratch ----------------------------------------------------
__device__ __align__(16) __half g_a16[(size_t)MROWS * DD];
__device__ __align__(16) __half g_wT_in[(size_t)NPROJ * DD];
__device__ __align__(16) __half g_wT_out[(size_t)DD * DD];
__device__ __align__(16) __half g_proj[(size_t)MROWS * NPROJ];
__device__ __align__(16) __half g_q16[(size_t)BB * HH * SS * HD];
__device__ __align__(16) __half g_k16[(size_t)BB * HH * SS * HD];
__device__ __align__(16) __half g_v16[(size_t)BB * HH * SS * HD];
__device__ __align__(16) __half g_x16[(size_t)MROWS * DD];
__device__ __align__(16) float2 g_sc[(size_t)MROWS * 32];   // (sin,cos) per (row, i)

// ---------------- PTX helpers ------------------------------------------------
__device__ __forceinline__ uint32_t smem_addr(const void* p) {
    return (uint32_t)__cvta_generic_to_shared(p);
}
__device__ __forceinline__ void cp16(uint32_t s, const void* g) {
    asm volatile("cp.async.cg.shared.global [%0], [%1], 16;\n" :: "r"(s), "l"(g));
}
__device__ __forceinline__ void cp_commit() { asm volatile("cp.async.commit_group;\n"); }
__device__ __forceinline__ void cp_wait1()  { asm volatile("cp.async.wait_group 1;\n"); }

__device__ __forceinline__ void ldm4(uint32_t& r0, uint32_t& r1, uint32_t& r2, uint32_t& r3, uint32_t a) {
    asm volatile("ldmatrix.sync.aligned.m8n8.x4.shared.b16 {%0,%1,%2,%3},[%4];\n"
                 : "=r"(r0), "=r"(r1), "=r"(r2), "=r"(r3) : "r"(a));
}
__device__ __forceinline__ void ldm4t(uint32_t& r0, uint32_t& r1, uint32_t& r2, uint32_t& r3, uint32_t a) {
    asm volatile("ldmatrix.sync.aligned.m8n8.x4.trans.shared.b16 {%0,%1,%2,%3},[%4];\n"
                 : "=r"(r0), "=r"(r1), "=r"(r2), "=r"(r3) : "r"(a));
}
__device__ __forceinline__ void mma16816(float* c,
    uint32_t a0, uint32_t a1, uint32_t a2, uint32_t a3, uint32_t b0, uint32_t b1) {
    asm volatile("mma.sync.aligned.m16n8k16.row.col.f32.f16.f16.f32 "
                 "{%0,%1,%2,%3},{%4,%5,%6,%7},{%8,%9},{%0,%1,%2,%3};\n"
                 : "+f"(c[0]), "+f"(c[1]), "+f"(c[2]), "+f"(c[3])
                 : "r"(a0), "r"(a1), "r"(a2), "r"(a3), "r"(b0), "r"(b1));
}
__device__ __forceinline__ float ex2f(float x) {
    float y; asm("ex2.approx.f32 %0,%1;\n" : "=f"(y) : "f"(x)); return y;
}
__device__ __forceinline__ uint32_t cvt_h2(float a, float b) {
    uint32_t r;
    asm("cvt.rn.f16x2.f32 %0, %1, %2;\n" : "=r"(r) : "f"(b), "f"(a));
    return r;
}
__device__ __forceinline__ uint32_t ex2_h2(uint32_t x) {
    uint32_t r;
    asm("ex2.approx.f16x2 %0, %1;\n" : "=r"(r) : "r"(x));
    return r;
}

#define L2E 1.4426950408889634f

// ---------------- convert f32 -> f16 ----------------------------------------
__global__ void cvt16_kernel(const float* __restrict__ A, __half* __restrict__ O) {
    int i = blockIdx.x * blockDim.x + threadIdx.x;
    float2 v = ((const float2*)A)[i];
    ((__half2*)O)[i] = __float22half2_rn(v);
}

// ---------------- transpose + convert: WT[c][r] = W[r][c] -------------------
__global__ void transcvt_kernel(const float* __restrict__ W, __half* __restrict__ WT,
                                int R, int C) {
    __shared__ float t[32][33];
    int c0 = blockIdx.x * 32, r0 = blockIdx.y * 32;
    int x = threadIdx.x, y = threadIdx.y;
#pragma unroll
    for (int i = 0; i < 32; i += 8)
        t[y + i][x] = W[(size_t)(r0 + y + i) * C + c0 + x];
    __syncthreads();
#pragma unroll
    for (int i = 0; i < 32; i += 8)
        WT[(size_t)(c0 + y + i) * R + r0 + x] = __float2half(t[x][y + i]);
}

// ---------------- sin/cos table: one entry per (row, i) ---------------------
__global__ void sincos_table(const int* __restrict__ segpos, float2* __restrict__ sc) {
    int idx = blockIdx.x * blockDim.x + threadIdx.x;   // over MROWS*32
    int i = idx & 31, row = idx >> 5;
    int pos = segpos[row];
    // 10000^(-i/32) = exp2(-i * log2(10000)/32)
    float inv = ex2f(-(float)i * 0.41524101186092037f);
    float ang = (float)pos * inv;
    float sn, cs;
    sincosf(ang, &sn, &cs);
    sc[idx] = make_float2(sn, cs);
}

// ---------------- HGEMM: C = A * B^T, BK=32, 3-stage, single-sync -----------
#define GST 40
#define HSTG (128 * GST)
template <typename OT>
__global__ __launch_bounds__(256, 2) void hgemm(
    const __half* __restrict__ A, const __half* __restrict__ B,
    OT* __restrict__ C, int M, int N, int K)
{
    extern __shared__ __half hsm[];
    __half* As = hsm;                 // 3 stages
    __half* Bs = hsm + 3 * HSTG;

    const int tid = threadIdx.x, lane = tid & 31, w = tid >> 5;
    const int wm = w & 1, wn = w >> 1;
    const int bx = blockIdx.x, by = blockIdx.y;
    const int nk = K >> 5;
    const int lrow = tid >> 2, lcol = (tid & 3) * 8;

    const __half* Ag = A + (size_t)(by * 128 + lrow) * K + lcol;
    const __half* Bg = B + (size_t)(bx * 128 + lrow) * K + lcol;
    const uint32_t sa0 = smem_addr(&As[lrow * GST + lcol]);
    const uint32_t sb0 = smem_addr(&Bs[lrow * GST + lcol]);
    const uint32_t stagesz = (uint32_t)(HSTG * sizeof(__half));

    float acc[4][4][4];
#pragma unroll
    for (int a = 0; a < 4; a++)
#pragma unroll
        for (int b = 0; b < 4; b++)
#pragma unroll
            for (int c = 0; c < 4; c++) acc[a][b][c] = 0.0f;

    // prologue: k-blocks 0,1 -> stages 0,1 (groups g0,g1)
#pragma unroll
    for (int p = 0; p < 2; p++) {
        const __half* ag = Ag + p * 32;
        const __half* bg = Bg + p * 32;
        cp16(sa0 + p * stagesz, ag);
        cp16(sa0 + p * stagesz + 64 * GST * 2, ag + (size_t)64 * K);
        cp16(sb0 + p * stagesz, bg);
        cp16(sb0 + p * stagesz + 64 * GST * 2, bg + (size_t)64 * K);
        cp_commit();
    }

    int st_r = 0;                      // kb % 3
    for (int kb = 0; kb < nk; kb++) {
        cp_wait1();                    // own copies for g_kb complete
        __syncthreads();               // ALL threads' g_kb complete; compute(kb-1) done
        int st_w = st_r - 1; if (st_w < 0) st_w = 2;
        if (kb + 2 < nk) {
            const __half* ag = Ag + (kb + 2) * 32;
            const __half* bg = Bg + (kb + 2) * 32;
            cp16(sa0 + st_w * stagesz, ag);
            cp16(sa0 + st_w * stagesz + 64 * GST * 2, ag + (size_t)64 * K);
            cp16(sb0 + st_w * stagesz, bg);
            cp16(sb0 + st_w * stagesz + 64 * GST * 2, bg + (size_t)64 * K);
        }
        cp_commit();                   // g_{kb+2}

        const __half* as = As + st_r * HSTG;
        const __half* bs = Bs + st_r * HSTG;
#pragma unroll
        for (int ks = 0; ks < 2; ks++) {
            uint32_t aq[4][4];
#pragma unroll
            for (int mi = 0; mi < 4; mi++) {
                uint32_t ad = smem_addr(as + (wm * 64 + mi * 16 + (lane & 15)) * GST
                                        + ks * 16 + 8 * (lane >> 4));
                ldm4(aq[mi][0], aq[mi][1], aq[mi][2], aq[mi][3], ad);
            }
#pragma unroll
            for (int nj = 0; nj < 2; nj++) {
                uint32_t b0, b1, b2, b3;
                uint32_t bd = smem_addr(bs + (wn * 32 + nj * 16 + (lane & 7) + 8 * (lane >> 4)) * GST
                                        + ks * 16 + 8 * ((lane >> 3) & 1));
                ldm4(b0, b1, b2, b3, bd);
#pragma unroll
                for (int mi = 0; mi < 4; mi++) {
                    mma16816(acc[mi][2 * nj],     aq[mi][0], aq[mi][1], aq[mi][2], aq[mi][3], b0, b1);
                    mma16816(acc[mi][2 * nj + 1], aq[mi][0], aq[mi][1], aq[mi][2], aq[mi][3], b2, b3);
                }
            }
        }
        st_r = (st_r == 2) ? 0 : st_r + 1;
    }

    // epilogue
#pragma unroll
    for (int mi = 0; mi < 4; mi++) {
#pragma unroll
        for (int ni = 0; ni < 4; ni++) {
            int row = by * 128 + wm * 64 + mi * 16 + (lane >> 2);
            int col = bx * 128 + wn * 32 + ni * 8 + 2 * (lane & 3);
            if (sizeof(OT) == 4) {
                *(float2*)((float*)C + (size_t)row * N + col) =
                    make_float2(acc[mi][ni][0], acc[mi][ni][1]);
                *(float2*)((float*)C + (size_t)(row + 8) * N + col) =
                    make_float2(acc[mi][ni][2], acc[mi][ni][3]);
            } else {
                *(__half2*)((__half*)C + (size_t)row * N + col) =
                    __float22half2_rn(make_float2(acc[mi][ni][0], acc[mi][ni][1]));
                *(__half2*)((__half*)C + (size_t)(row + 8) * N + col) =
                    __float22half2_rn(make_float2(acc[mi][ni][2], acc[mi][ni][3]));
            }
        }
    }
}

// ---------------- RoPE apply (table lookup) ---------------------------------
__global__ __launch_bounds__(256) void rope_kernel(
    const __half* __restrict__ proj, const float2* __restrict__ sc,
    __half* __restrict__ q, __half* __restrict__ k, __half* __restrict__ v)
{
    int idx = blockIdx.x * blockDim.x + threadIdx.x;
    int i = idx & 31;
    int h = (idx >> 5) & 15;
    int s = (idx >> 9) & 2047;
    int b = idx >> 20;

    int row = b * SS + s;
    const __half* p = proj + (size_t)row * NPROJ + h * (3 * HD);

    float2 t = sc[row * 32 + i];
    float sn = t.x, cs = t.y;

    float qf = __half2float(p[i]),          qs = __half2float(p[i + 32]);
    float kf = __half2float(p[HD + i]),     ks = __half2float(p[HD + i + 32]);
    __half vf = p[2 * HD + i],              vs = p[2 * HD + i + 32];

    const float qscale = 0.125f;
    size_t ob = ((size_t)(b * HH + h) * SS + s) * HD;
    q[ob + i]      = __float2half((qf * cs - qs * sn) * qscale);
    q[ob + i + 32] = __float2half((qs * cs + qf * sn) * qscale);
    k[ob + i]      = __float2half(kf * cs - ks * sn);
    k[ob + i + 32] = __float2half(ks * cs + kf * sn);
    v[ob + i]      = vf;
    v[ob + i + 32] = vs;
}

// ---------------- Flash attention: 128-row chunks, h2-exp + mma row-sum -----
#define FST 72
#define QSZ (128 * FST)
#define KVCH (128 * FST)
__global__ __launch_bounds__(256, 2) void flash16(
    const __half* __restrict__ Q, const __half* __restrict__ K,
    const __half* __restrict__ V, __half* __restrict__ X)
{
    extern __shared__ __half fsm[];
    __half* sQ = fsm;
    __half* sKs[2] = { fsm + QSZ, fsm + QSZ + KVCH };
    __half* sVs[2] = { fsm + QSZ + 2 * KVCH, fsm + QSZ + 3 * KVCH };

    const int tid = threadIdx.x, lane = tid & 31, w = tid >> 5;
    const int qb = (int)gridDim.x - 1 - (int)blockIdx.x;   // long CTAs first
    const int h = blockIdx.y, b = blockIdx.z;
    const int q0 = qb * 128, m0 = w * 16;
    const size_t base = (size_t)(b * HH + h) * SS * HD;

    const int lr = tid >> 3, lc = (tid & 7) * 8;

    // prologue: Q + KV chunk 0 -> one group
    {
#pragma unroll
        for (int p = 0; p < 4; p++) {
            cp16(smem_addr(&sQ[(lr + p * 32) * FST + lc]),
                 Q + base + (size_t)(q0 + lr + p * 32) * HD + lc);
            cp16(smem_addr(&sKs[0][(lr + p * 32) * FST + lc]),
                 K + base + (size_t)(lr + p * 32) * HD + lc);
            cp16(smem_addr(&sVs[0][(lr + p * 32) * FST + lc]),
                 V + base + (size_t)(lr + p * 32) * HD + lc);
        }
        cp_commit();
    }

    uint32_t aq[4][4];
    float Ov[8][4];
#pragma unroll
    for (int t = 0; t < 8; t++)
#pragma unroll
        for (int c = 0; c < 4; c++) Ov[t][c] = 0.0f;
    float mA = -1e30f, mB = -1e30f, lA = 0.0f, lB = 0.0f;

    const int nch = qb + 1;
    for (int ch = 0; ch < nch; ch++) {
        if (ch + 1 < nch) {
            int st = (ch + 1) & 1;
#pragma unroll
            for (int p = 0; p < 4; p++) {
                cp16(smem_addr(&sKs[st][(lr + p * 32) * FST + lc]),
                     K + base + (size_t)((ch + 1) * 128 + lr + p * 32) * HD + lc);
                cp16(smem_addr(&sVs[st][(lr + p * 32) * FST + lc]),
                     V + base + (size_t)((ch + 1) * 128 + lr + p * 32) * HD + lc);
            }
        }
        cp_commit();
        cp_wait1();
        __syncthreads();

        if (ch == 0) {
#pragma unroll
            for (int ks = 0; ks < 4; ks++) {
                uint32_t ad = smem_addr(&sQ[(m0 + (lane & 15)) * FST + ks * 16 + 8 * (lane >> 4)]);
                ldm4(aq[ks][0], aq[ks][1], aq[ks][2], aq[ks][3], ad);
            }
        }

        const __half* sKc = sKs[ch & 1];
        const __half* sVc = sVs[ch & 1];

#pragma unroll
        for (int sub = 0; sub < 2; sub++) {
            const int kv0 = ch * 128 + sub * 64;
            if (kv0 > q0 + m0 + 15) continue;      // warp rows fully masked
            const __half* sK = sKc + sub * 64 * FST;
            const __half* sV = sVc + sub * 64 * FST;

            float Sv[8][4];
#pragma unroll
            for (int t = 0; t < 8; t++)
#pragma unroll
                for (int c = 0; c < 4; c++) Sv[t][c] = 0.0f;

#pragma unroll
            for (int ks = 0; ks < 4; ks++) {
#pragma unroll
                for (int ng = 0; ng < 4; ng++) {
                    uint32_t b0, b1, b2, b3;
                    uint32_t bd = smem_addr(&sK[(ng * 16 + (lane & 7) + 8 * (lane >> 4)) * FST
                                                + ks * 16 + 8 * ((lane >> 3) & 1)]);
                    ldm4(b0, b1, b2, b3, bd);
                    mma16816(Sv[2 * ng],     aq[ks][0], aq[ks][1], aq[ks][2], aq[ks][3], b0, b1);
                    mma16816(Sv[2 * ng + 1], aq[ks][0], aq[ks][1], aq[ks][2], aq[ks][3], b2, b3);
                }
            }

            // softcap (poly tanh) + causal mask
            const bool domask = (kv0 + 63 > q0 + m0);
            const int rAg = q0 + m0 + (lane >> 2);
            const int rBg = rAg + 8;
#pragma unroll
            for (int t = 0; t < 8; t++) {
                int cg = kv0 + t * 8 + 2 * (lane & 3);
#pragma unroll
                for (int c = 0; c < 4; c++) {
                    float s = Sv[t][c];
                    float x = 0.02f * s;
                    float x2 = x * x;
                    s = fmaf(s * x2, fmaf(0.13333334f, x2, -0.33333334f), s);
                    if (domask) {
                        int colg = cg + (c & 1);
                        int rowg = (c < 2) ? rAg : rBg;
                        if (colg > rowg) s = -1e30f;
                    }
                    Sv[t][c] = s;
                }
            }

            // online softmax: row max
            float tmA = -1e30f, tmB = -1e30f;
#pragma unroll
            for (int t = 0; t < 8; t++) {
                tmA = fmaxf(tmA, fmaxf(Sv[t][0], Sv[t][1]));
                tmB = fmaxf(tmB, fmaxf(Sv[t][2], Sv[t][3]));
            }
            tmA = fmaxf(tmA, __shfl_xor_sync(0xffffffffu, tmA, 1));
            tmA = fmaxf(tmA, __shfl_xor_sync(0xffffffffu, tmA, 2));
            tmB = fmaxf(tmB, __shfl_xor_sync(0xffffffffu, tmB, 1));
            tmB = fmaxf(tmB, __shfl_xor_sync(0xffffffffu, tmB, 2));
            float mnA = fmaxf(mA, tmA), mnB = fmaxf(mB, tmB);
            float alA = ex2f((mA - mnA) * L2E);
            float alB = ex2f((mB - mnB) * L2E);
            mA = mnA; mB = mnB;
            float mlA = mnA * L2E, mlB = mnB * L2E;

            // exp via f16x2 MUFU; results ARE the PV A-fragments
            uint32_t Pa[8], Pb[8];
#pragma unroll
            for (int t = 0; t < 8; t++) {
                float eA0 = fmaf(Sv[t][0], L2E, -mlA);
                float eA1 = fmaf(Sv[t][1], L2E, -mlA);
                float eB0 = fmaf(Sv[t][2], L2E, -mlB);
                float eB1 = fmaf(Sv[t][3], L2E, -mlB);
                Pa[t] = ex2_h2(cvt_h2(eA0, eA1));
                Pb[t] = ex2_h2(cvt_h2(eB0, eB1));
            }

            // row sums via mma with all-ones B
            float sacc[4] = {0.0f, 0.0f, 0.0f, 0.0f};
            const uint32_t ones2 = 0x3C003C00u;
#pragma unroll
            for (int ks2 = 0; ks2 < 4; ks2++)
                mma16816(sacc, Pa[2 * ks2], Pb[2 * ks2], Pa[2 * ks2 + 1], Pb[2 * ks2 + 1],
                         ones2, ones2);
            lA = lA * alA + sacc[0];
            lB = lB * alB + sacc[2];

#pragma unroll
            for (int t = 0; t < 8; t++) {
                Ov[t][0] *= alA; Ov[t][1] *= alA;
                Ov[t][2] *= alB; Ov[t][3] *= alB;
            }

            // PV
#pragma unroll
            for (int ks2 = 0; ks2 < 4; ks2++) {
                uint32_t a0 = Pa[2 * ks2];
                uint32_t a1 = Pb[2 * ks2];
                uint32_t a2 = Pa[2 * ks2 + 1];
                uint32_t a3 = Pb[2 * ks2 + 1];
#pragma unroll
                for (int dg = 0; dg < 4; dg++) {
                    uint32_t b0, b1, b2, b3;
                    uint32_t bd = smem_addr(&sV[(ks2 * 16 + (lane & 7) + 8 * ((lane >> 3) & 1)) * FST
                                                + dg * 16 + 8 * (lane >> 4)]);
                    ldm4t(b0, b1, b2, b3, bd);
                    mma16816(Ov[2 * dg],     a0, a1, a2, a3, b0, b1);
                    mma16816(Ov[2 * dg + 1], a0, a1, a2, a3, b2, b3);
                }
            }
        }
        __syncthreads();
    }

    // normalize + write x16[token][h*64 + d]
    float iA = 1.0f / lA, iB = 1.0f / lB;
    int rowA = b * SS + q0 + m0 + (lane >> 2);
#pragma unroll
    for (int t = 0; t < 8; t++) {
        int col = h * 64 + t * 8 + 2 * (lane & 3);
        *(__half2*)(X + (size_t)rowA * DD + col) =
            __float22half2_rn(make_float2(Ov[t][0] * iA, Ov[t][1] * iA));
        *(__half2*)(X + (size_t)(rowA + 8) * DD + col) =
            __float22half2_rn(make_float2(Ov[t][2] * iB, Ov[t][3] * iB));
    }
}

// ---------------- launch ----------------------------------------------------
extern "C" void kernel_launch(void* const* d_in, const int* in_sizes, int n_in,
                              void* d_out, int out_size)
{
    const float* inputs = (const float*)d_in[0];
    const int*   segpos = (const int*)d_in[1];
    const float* w_in   = (const float*)d_in[3];
    const float* w_out  = (const float*)d_in[4];
    float* out = (float*)d_out;

    __half *a16, *wTin, *wTout, *proj, *q16, *k16, *v16, *x16;
    float2* sc;
    cudaGetSymbolAddress((void**)&a16,  g_a16);
    cudaGetSymbolAddress((void**)&wTin, g_wT_in);
    cudaGetSymbolAddress((void**)&wTout,g_wT_out);
    cudaGetSymbolAddress((void**)&proj, g_proj);
    cudaGetSymbolAddress((void**)&q16,  g_q16);
    cudaGetSymbolAddress((void**)&k16,  g_k16);
    cudaGetSymbolAddress((void**)&v16,  g_v16);
    cudaGetSymbolAddress((void**)&x16,  g_x16);
    cudaGetSymbolAddress((void**)&sc,   g_sc);

    const int hgemm_smem = 3 * 2 * HSTG * (int)sizeof(__half);     // 61440
    const int flash_smem = (QSZ + 4 * KVCH) * (int)sizeof(__half); // 92160
    cudaFuncSetAttribute(hgemm<__half>, cudaFuncAttributeMaxDynamicSharedMemorySize, hgemm_smem);
    cudaFuncSetAttribute(hgemm<float>,  cudaFuncAttributeMaxDynamicSharedMemorySize, hgemm_smem);
    cudaFuncSetAttribute(flash16, cudaFuncAttributeMaxDynamicSharedMemorySize, flash_smem);

    // converts + trig table (independent of GEMM)
    cvt16_kernel<<<(MROWS * DD / 2) / 256, 256>>>(inputs, a16);
    transcvt_kernel<<<dim3(NPROJ / 32, DD / 32), dim3(32, 8)>>>(w_in, wTin, DD, NPROJ);
    transcvt_kernel<<<dim3(DD / 32, DD / 32), dim3(32, 8)>>>(w_out, wTout, DD, DD);
    sincos_table<<<(MROWS * 32) / 256, 256>>>(segpos, sc);

    // 1) QKV projection -> f16 proj
    hgemm<__half><<<dim3(NPROJ / 128, MROWS / 128), 256, hgemm_smem>>>(a16, wTin, proj, MROWS, NPROJ, DD);

    // 2) RoPE + split (table lookup)
    rope_kernel<<<(BB * SS * HH * 32) / 256, 256>>>(proj, sc, q16, k16, v16);

    // 3) flash attention
    flash16<<<dim3(SS / 128, HH, BB), 256, flash_smem>>>(q16, k16, v16, x16);

    // 4) output projection -> f32 out
    hgemm<float><<<dim3(DD / 128, MROWS / 128), 256, hgemm_smem>>>(x16, wTout, out, MROWS, DD, DD);
}